// round 16
// baseline (speedup 1.0000x reference)
#include <cuda_runtime.h>
#include <cuda_bf16.h>
#include <cstdint>
#include <math.h>

// ============================================================
// x(1024,512) f32, prototypes(100,10,512) f32, log_dist_scales(100,10,512) f32
// out(1024,100) = logsumexp_p( -( sum_d w*(x-p)^2 ) ),  w = exp(ls)
// dist = t1 + (-2*t2 + t3)
// R16: continue R15's winning iteration-halving: stage = QUAD (BK=256),
// fast path = 2 pipeline iterations (was 4). 104KB SMEM, 2 CTAs/SM.
// Prep: warp-uniform expf skip when ls==0 (w=1 exactly) — removes ~512K MUFU.
// Fast path (ls==0): K=512, t1 slid out of LSE.
// ============================================================

#define MB 1024
#define KD 1024

#define BM 64
#define BN 40
#define NKQ 4            // k-quads of 4x64 cols; fast path starts at 2
#define NTHREADS 128

// ---------------- device scratch ----------------
__device__ __nv_bfloat16 g_A[MB * KD];     // [b][k]  k<512: x^2, k>=512: x
__device__ __nv_bfloat16 g_Bm[1000 * KD];  // [cp][k] k<512: w,   k>=512: -2wp
__device__ float g_t3[1000];               // sum w p^2
__device__ float g_t1[MB];                 // sum x^2 (fp32 exact)
__device__ int   g_flag;                   // sticky: 1 if any ls != 0 (zero-init)

// ---------------- helpers ----------------
__device__ __forceinline__ uint32_t smem_u32(const void* p) {
    uint32_t a;
    asm("{ .reg .u64 t; cvta.to.shared.u64 t, %1; cvt.u32.u64 %0, t; }" : "=r"(a) : "l"(p));
    return a;
}
__device__ __forceinline__ uint32_t sw128(uint32_t off) {
    return off ^ ((off >> 3) & 0x70);
}
#define CP_ASYNC16(dst, src) \
    asm volatile("cp.async.cg.shared.global [%0], [%1], 16;" :: "r"(dst), "l"(src) : "memory")
#define CP_COMMIT() asm volatile("cp.async.commit_group;" ::: "memory")
#define CP_WAIT1()  asm volatile("cp.async.wait_group 1;" ::: "memory")
#define CP_WAIT0()  asm volatile("cp.async.wait_group 0;" ::: "memory")

#define LDMATRIX_X4(r0, r1, r2, r3, addr) \
    asm volatile("ldmatrix.sync.aligned.m8n8.x4.shared.b16 {%0,%1,%2,%3}, [%4];" \
                 : "=r"(r0), "=r"(r1), "=r"(r2), "=r"(r3) : "r"(addr))
#define LDMATRIX_X2(r0, r1, addr) \
    asm volatile("ldmatrix.sync.aligned.m8n8.x2.shared.b16 {%0,%1}, [%2];" \
                 : "=r"(r0), "=r"(r1) : "r"(addr))
#define MMA_16816(c0, c1, c2, c3, a0, a1, a2, a3, b0, b1) \
    asm volatile("mma.sync.aligned.m16n8k16.row.col.f32.bf16.bf16.f32 " \
                 "{%0,%1,%2,%3}, {%4,%5,%6,%7}, {%8,%9}, {%0,%1,%2,%3};" \
                 : "+f"(c0), "+f"(c1), "+f"(c2), "+f"(c3) \
                 : "r"(a0), "r"(a1), "r"(a2), "r"(a3), "r"(b0), "r"(b1))

// ---------------- prep: x + t1 (blocks 0..255), proto + t3 + flag (256..755)
__global__ void prep_kernel(const float* __restrict__ x,
                            const float* __restrict__ proto,
                            const float* __restrict__ ls) {
    const int tid = threadIdx.x;
    if (blockIdx.x < 256) {
        int idx = blockIdx.x * 256 + tid;
        int b  = idx >> 6;
        int d0 = (idx & 63) * 8;
        const float4* src = reinterpret_cast<const float4*>(x) + idx * 2;
        float4 v0 = src[0], v1 = src[1];
        __nv_bfloat162 hs[4], hx[4];
        hs[0] = __floats2bfloat162_rn(v0.x * v0.x, v0.y * v0.y);
        hs[1] = __floats2bfloat162_rn(v0.z * v0.z, v0.w * v0.w);
        hs[2] = __floats2bfloat162_rn(v1.x * v1.x, v1.y * v1.y);
        hs[3] = __floats2bfloat162_rn(v1.z * v1.z, v1.w * v1.w);
        hx[0] = __floats2bfloat162_rn(v0.x, v0.y);
        hx[1] = __floats2bfloat162_rn(v0.z, v0.w);
        hx[2] = __floats2bfloat162_rn(v1.x, v1.y);
        hx[3] = __floats2bfloat162_rn(v1.z, v1.w);
        *reinterpret_cast<uint4*>(g_A + (size_t)b * KD + d0)       = *reinterpret_cast<uint4*>(hs);
        *reinterpret_cast<uint4*>(g_A + (size_t)b * KD + 512 + d0) = *reinterpret_cast<uint4*>(hx);
        float s = v0.x * v0.x + v0.y * v0.y + v0.z * v0.z + v0.w * v0.w
                + v1.x * v1.x + v1.y * v1.y + v1.z * v1.z + v1.w * v1.w;
        #pragma unroll
        for (int o = 16; o > 0; o >>= 1) s += __shfl_xor_sync(0xffffffffu, s, o);
        __shared__ float red[8];
        if ((tid & 31) == 0) red[tid >> 5] = s;
        __syncthreads();
        if ((tid & 63) == 0) {
            int w0 = tid >> 5;
            g_t1[b] = red[w0] + red[w0 + 1];
        }
    } else {
        int cp = (blockIdx.x - 256) * 2 + (tid >> 7);
        int d0 = (tid & 127) * 4;
        float4 lw = *reinterpret_cast<const float4*>(ls + (size_t)cp * 512 + d0);
        float4 pv = *reinterpret_cast<const float4*>(proto + (size_t)cp * 512 + d0);
        bool nzb = (lw.x != 0.f) || (lw.y != 0.f) || (lw.z != 0.f) || (lw.w != 0.f);
        unsigned nz = __ballot_sync(0xffffffffu, nzb);
        float acc;
        if (nz) {
            if ((tid & 31) == 0) atomicOr(&g_flag, 1);   // sticky across replays
            float w0 = expf(lw.x), w1 = expf(lw.y), w2 = expf(lw.z), w3 = expf(lw.w);
            __nv_bfloat162 hw[2], hp[2];
            hw[0] = __floats2bfloat162_rn(w0, w1);
            hw[1] = __floats2bfloat162_rn(w2, w3);
            hp[0] = __floats2bfloat162_rn(-2.0f * w0 * pv.x, -2.0f * w1 * pv.y);
            hp[1] = __floats2bfloat162_rn(-2.0f * w2 * pv.z, -2.0f * w3 * pv.w);
            *reinterpret_cast<uint2*>(g_Bm + (size_t)cp * KD + d0)       = *reinterpret_cast<uint2*>(hw);
            *reinterpret_cast<uint2*>(g_Bm + (size_t)cp * KD + 512 + d0) = *reinterpret_cast<uint2*>(hp);
            acc = w0 * pv.x * pv.x + w1 * pv.y * pv.y + w2 * pv.z * pv.z + w3 * pv.w * pv.w;
        } else {
            // warp-uniform fast path: w = exp(0) = 1 exactly
            uint2 ones = make_uint2(0x3F803F80u, 0x3F803F80u);   // bf16 1.0 x4
            __nv_bfloat162 hp[2];
            hp[0] = __floats2bfloat162_rn(-2.0f * pv.x, -2.0f * pv.y);
            hp[1] = __floats2bfloat162_rn(-2.0f * pv.z, -2.0f * pv.w);
            *reinterpret_cast<uint2*>(g_Bm + (size_t)cp * KD + d0)       = ones;
            *reinterpret_cast<uint2*>(g_Bm + (size_t)cp * KD + 512 + d0) = *reinterpret_cast<uint2*>(hp);
            acc = pv.x * pv.x + pv.y * pv.y + pv.z * pv.z + pv.w * pv.w;
        }
        #pragma unroll
        for (int o = 16; o > 0; o >>= 1) acc += __shfl_xor_sync(0xffffffffu, acc, o);
        __shared__ float red2[8];
        if ((tid & 31) == 0) red2[tid >> 5] = acc;
        __syncthreads();
        if ((tid & 127) == 0) {
            int w0i = (tid >> 7) * 4;
            g_t3[cp] = red2[w0i] + red2[w0i + 1] + red2[w0i + 2] + red2[w0i + 3];
        }
    }
}

// ---------------- GEMM + fused LSE: BM=64/BN=40, 128 thr, stage = QUAD (BK=256) ----------------
// Stage: A 4x[64][64] bf16 = 32KB (sub-tiles at +h*8192), B 4x[40][64] = 20KB (+h*5120).
// A stages at s*32768; B at 65536 + s*20480. Total 104KB -> 2 CTAs/SM.
#define SA_OFF(s) ((s) * 32768)
#define SB_OFF(s) (65536 + (s) * 20480)
#define SMEM_TOTAL  (65536 + 2 * 20480)     // 106496
#define SST_STRIDE  44
#define T3_OFF      (64 * SST_STRIDE * 4)   // 11264 (inside stage-0 A, post-loop use)

__global__ __launch_bounds__(NTHREADS, 2) void gemm_lse_kernel(float* __restrict__ out) {
    extern __shared__ char smem[];
    const uint32_t sbase = smem_u32(smem);
    const int tid = threadIdx.x;
    const int wid = tid >> 5;    // 0..3
    const int lid = tid & 31;
    const int m0 = blockIdx.y * BM;
    const int n0 = blockIdx.x * BN;

    const int flag = g_flag;
    const int kq_start = flag ? 0 : 2;   // quad q covers cols q*256..q*256+255

    float t3reg = (tid < 40) ? g_t3[n0 + tid] : 0.f;

    // ---- A load plan: per stage 2048 chunks; thread handles (j,h) j=0..3,h=0..3.
    // For tid<128: chunk q = tid + 128*(4h + j) has h = i>>2 exactly, so
    // r = (tid>>3) + 16*j, c = tid&7; gmem advance per h = 8 uint4, per quad = 32.
    const int arb = tid >> 3;        // row base 0..15
    const int ac  = tid & 7;
    const uint4* a_row[4];
    uint32_t a_off[4];
    #pragma unroll
    for (int j = 0; j < 4; j++) {
        int r = arb + 16 * j;
        a_row[j] = reinterpret_cast<const uint4*>(g_A + (size_t)(m0 + r) * KD) + ac;
        a_off[j] = sw128((uint32_t)r * 128u + (uint32_t)ac * 16u);
    }
    // ---- B load plan: per stage 1280 chunks, 10/thread, linear map.
    const uint4* b_gb[10];
    uint32_t b_off[10];
    #pragma unroll
    for (int i = 0; i < 10; i++) {
        int q = tid + i * NTHREADS;    // [0,1280)
        int h = q / 320, qq = q % 320;
        int r = qq >> 3, c = qq & 7;
        b_gb[i] = reinterpret_cast<const uint4*>(g_Bm + (size_t)(n0 + r) * KD) + h * 8 + c;
        b_off[i] = (uint32_t)h * 5120u + sw128((uint32_t)r * 128u + (uint32_t)c * 16u);
    }

    // warp layout: 4 warps stacked in M; warp tile 16 x 40 (R11/R15-verified)
    const int wm = wid * 16;

    float acc[5][4];
    #pragma unroll
    for (int nf = 0; nf < 5; nf++)
        #pragma unroll
        for (int i = 0; i < 4; i++) acc[nf][i] = 0.f;

    // ldmatrix swizzled offsets within a 64-col sub-tile
    const int l4 = lid & 15;
    uint32_t a_lm_off[4];
    uint32_t b4_off[2][4];
    uint32_t b2_off[4];
    #pragma unroll
    for (int ks = 0; ks < 4; ks++) {
        {
            uint32_t r = wm + (lid & 15);
            uint32_t ch = ks * 2 + (lid >> 4);
            a_lm_off[ks] = sw128(r * 128u + ch * 16u);
        }
        #pragma unroll
        for (int j = 0; j < 2; j++) {
            uint32_t r = j * 16 + (lid >> 4) * 8 + (lid & 7);
            uint32_t ch = ks * 2 + ((lid >> 3) & 1);
            b4_off[j][ks] = sw128(r * 128u + ch * 16u);
        }
        {
            uint32_t r = 32 + (l4 & 7);
            uint32_t ch = ks * 2 + (l4 >> 3);
            b2_off[ks] = sw128(r * 128u + ch * 16u);
        }
    }

    // ---- prologue: load quad kq_start ----
    {
        int s = kq_start & 1;
        uint32_t sa = sbase + SA_OFF(s), sb = sbase + SB_OFF(s);
        #pragma unroll
        for (int j = 0; j < 4; j++)
            #pragma unroll
            for (int h = 0; h < 4; h++)
                CP_ASYNC16(sa + h * 8192u + a_off[j], a_row[j] + kq_start * 32 + h * 8);
        #pragma unroll
        for (int i = 0; i < 10; i++) CP_ASYNC16(sb + b_off[i], b_gb[i] + kq_start * 32);
        CP_COMMIT();
    }

    for (int kq = kq_start; kq < NKQ; kq++) {
        if (kq + 1 < NKQ) {
            int ns = (kq + 1) & 1;
            uint32_t sa = sbase + SA_OFF(ns), sb = sbase + SB_OFF(ns);
            #pragma unroll
            for (int j = 0; j < 4; j++)
                #pragma unroll
                for (int h = 0; h < 4; h++)
                    CP_ASYNC16(sa + h * 8192u + a_off[j], a_row[j] + (kq + 1) * 32 + h * 8);
            #pragma unroll
            for (int i = 0; i < 10; i++) CP_ASYNC16(sb + b_off[i], b_gb[i] + (kq + 1) * 32);
            CP_COMMIT();
            CP_WAIT1();
        } else {
            CP_WAIT0();
        }
        __syncthreads();   // one barrier per QUAD of k-tiles

        const uint32_t sa = sbase + SA_OFF(kq & 1);
        const uint32_t sb = sbase + SB_OFF(kq & 1);
        #pragma unroll
        for (int h = 0; h < 4; h++) {
            const uint32_t ah = sa + h * 8192u;
            const uint32_t bh = sb + h * 5120u;
            #pragma unroll
            for (int ks = 0; ks < 4; ks++) {
                uint32_t a[4], b[5][2];
                LDMATRIX_X4(a[0], a[1], a[2], a[3], ah + a_lm_off[ks]);
                LDMATRIX_X4(b[0][0], b[0][1], b[1][0], b[1][1], bh + b4_off[0][ks]);
                LDMATRIX_X4(b[2][0], b[2][1], b[3][0], b[3][1], bh + b4_off[1][ks]);
                LDMATRIX_X2(b[4][0], b[4][1], bh + b2_off[ks]);
                #pragma unroll
                for (int nf = 0; nf < 5; nf++)
                    MMA_16816(acc[nf][0], acc[nf][1], acc[nf][2], acc[nf][3],
                              a[0], a[1], a[2], a[3], b[nf][0], b[nf][1]);
            }
        }
        __syncthreads();
    }

    // ---- fused epilogue: fragments -> SMEM stage -> per-(row,class) logsumexp ----
    float* sst = reinterpret_cast<float*>(smem);            // [64][44]
    float* st3 = reinterpret_cast<float*>(smem + T3_OFF);   // [40]
    if (tid < 40) st3[tid] = t3reg;

    const int qr = lid >> 2;
    const int qc = (lid & 3) * 2;
    {
        int row = wm + qr;
        #pragma unroll
        for (int nf = 0; nf < 5; nf++) {
            int col = nf * 8 + qc;
            *reinterpret_cast<float2*>(&sst[row * SST_STRIDE + col]) =
                make_float2(acc[nf][0], acc[nf][1]);
            *reinterpret_cast<float2*>(&sst[(row + 8) * SST_STRIDE + col]) =
                make_float2(acc[nf][2], acc[nf][3]);
        }
    }
    __syncthreads();

    // 64 rows x 4 classes = 256 tasks, 2 per thread
    const int c0 = blockIdx.x * 4;
    #pragma unroll
    for (int i = 0; i < 2; i++) {
        int task = tid + i * NTHREADS;
        int row = task >> 2;
        int cls = task & 3;
        const float* sp = &sst[row * SST_STRIDE + cls * 10];
        const float* tp = &st3[cls * 10];
        float v[10], mx = -3.4e38f;
        #pragma unroll
        for (int p = 0; p < 10; p++) {
            v[p] = -(sp[p] + tp[p]);
            mx = fmaxf(mx, v[p]);
        }
        float s = 0.f;
        #pragma unroll
        for (int p = 0; p < 10; p++) s += expf(v[p] - mx);
        float t1v = flag ? 0.f : g_t1[m0 + row];   // fast path: t1 slid out of lse
        out[(size_t)(m0 + row) * 100 + c0 + cls] = mx + logf(s) - t1v;
    }
}

// ---------------- launch ----------------
extern "C" void kernel_launch(void* const* d_in, const int* in_sizes, int n_in,
                              void* d_out, int out_size) {
    const float* x     = (const float*)d_in[0];  // (1024, 512)
    const float* proto = (const float*)d_in[1];  // (100, 10, 512)
    const float* ls    = (const float*)d_in[2];  // (100, 10, 512)
    float* out = (float*)d_out;                  // (1024, 100)

    cudaFuncSetAttribute(gemm_lse_kernel, cudaFuncAttributeMaxDynamicSharedMemorySize, SMEM_TOTAL);

    prep_kernel<<<756, 256>>>(x, proto, ls);     // x+t1 (256 blocks) | proto+t3+flag (500)
    gemm_lse_kernel<<<dim3(25, MB / BM), NTHREADS, SMEM_TOTAL>>>(out);
}

// round 17
// speedup vs baseline: 1.1169x; 1.1169x over previous
#include <cuda_runtime.h>
#include <cuda_bf16.h>
#include <cstdint>
#include <math.h>

// ============================================================
// x(1024,512) f32, prototypes(100,10,512) f32, log_dist_scales(100,10,512) f32
// out(1024,100) = logsumexp_p( -( sum_d w*(x-p)^2 ) ),  w = exp(ls)
// dist = t1 + (-2*t2 + t3)
// R17: recombination of verified components.
//   GEMM  = R15 verbatim (stage = k-pair BK=128, 4 warps 16x40, 400 tiles,
//           3 CTAs/SM) -> measured 9.70us.
//   Prep  = R16 verbatim (warp-uniform expf skip when ls==0) -> measured
//           non-gemm 1.95us.
// Fast path (ls==0): K=512, t1 slid out of LSE.
// ============================================================

#define MB 1024
#define KD 1024

#define BM 64
#define BN 40
#define NKP 8            // k-pairs of 2x64; fast path starts at 4
#define NTHREADS 128

// ---------------- device scratch ----------------
__device__ __nv_bfloat16 g_A[MB * KD];     // [b][k]  k<512: x^2, k>=512: x
__device__ __nv_bfloat16 g_Bm[1000 * KD];  // [cp][k] k<512: w,   k>=512: -2wp
__device__ float g_t3[1000];               // sum w p^2
__device__ float g_t1[MB];                 // sum x^2 (fp32 exact)
__device__ int   g_flag;                   // sticky: 1 if any ls != 0 (zero-init)

// ---------------- helpers ----------------
__device__ __forceinline__ uint32_t smem_u32(const void* p) {
    uint32_t a;
    asm("{ .reg .u64 t; cvta.to.shared.u64 t, %1; cvt.u32.u64 %0, t; }" : "=r"(a) : "l"(p));
    return a;
}
__device__ __forceinline__ uint32_t sw128(uint32_t off) {
    return off ^ ((off >> 3) & 0x70);
}
#define CP_ASYNC16(dst, src) \
    asm volatile("cp.async.cg.shared.global [%0], [%1], 16;" :: "r"(dst), "l"(src) : "memory")
#define CP_COMMIT() asm volatile("cp.async.commit_group;" ::: "memory")
#define CP_WAIT1()  asm volatile("cp.async.wait_group 1;" ::: "memory")
#define CP_WAIT0()  asm volatile("cp.async.wait_group 0;" ::: "memory")

#define LDMATRIX_X4(r0, r1, r2, r3, addr) \
    asm volatile("ldmatrix.sync.aligned.m8n8.x4.shared.b16 {%0,%1,%2,%3}, [%4];" \
                 : "=r"(r0), "=r"(r1), "=r"(r2), "=r"(r3) : "r"(addr))
#define LDMATRIX_X2(r0, r1, addr) \
    asm volatile("ldmatrix.sync.aligned.m8n8.x2.shared.b16 {%0,%1}, [%2];" \
                 : "=r"(r0), "=r"(r1) : "r"(addr))
#define MMA_16816(c0, c1, c2, c3, a0, a1, a2, a3, b0, b1) \
    asm volatile("mma.sync.aligned.m16n8k16.row.col.f32.bf16.bf16.f32 " \
                 "{%0,%1,%2,%3}, {%4,%5,%6,%7}, {%8,%9}, {%0,%1,%2,%3};" \
                 : "+f"(c0), "+f"(c1), "+f"(c2), "+f"(c3) \
                 : "r"(a0), "r"(a1), "r"(a2), "r"(a3), "r"(b0), "r"(b1))

// ---------------- prep (R16): x + t1 (blocks 0..255), proto + t3 + flag (256..755)
__global__ void prep_kernel(const float* __restrict__ x,
                            const float* __restrict__ proto,
                            const float* __restrict__ ls) {
    const int tid = threadIdx.x;
    if (blockIdx.x < 256) {
        int idx = blockIdx.x * 256 + tid;
        int b  = idx >> 6;
        int d0 = (idx & 63) * 8;
        const float4* src = reinterpret_cast<const float4*>(x) + idx * 2;
        float4 v0 = src[0], v1 = src[1];
        __nv_bfloat162 hs[4], hx[4];
        hs[0] = __floats2bfloat162_rn(v0.x * v0.x, v0.y * v0.y);
        hs[1] = __floats2bfloat162_rn(v0.z * v0.z, v0.w * v0.w);
        hs[2] = __floats2bfloat162_rn(v1.x * v1.x, v1.y * v1.y);
        hs[3] = __floats2bfloat162_rn(v1.z * v1.z, v1.w * v1.w);
        hx[0] = __floats2bfloat162_rn(v0.x, v0.y);
        hx[1] = __floats2bfloat162_rn(v0.z, v0.w);
        hx[2] = __floats2bfloat162_rn(v1.x, v1.y);
        hx[3] = __floats2bfloat162_rn(v1.z, v1.w);
        *reinterpret_cast<uint4*>(g_A + (size_t)b * KD + d0)       = *reinterpret_cast<uint4*>(hs);
        *reinterpret_cast<uint4*>(g_A + (size_t)b * KD + 512 + d0) = *reinterpret_cast<uint4*>(hx);
        float s = v0.x * v0.x + v0.y * v0.y + v0.z * v0.z + v0.w * v0.w
                + v1.x * v1.x + v1.y * v1.y + v1.z * v1.z + v1.w * v1.w;
        #pragma unroll
        for (int o = 16; o > 0; o >>= 1) s += __shfl_xor_sync(0xffffffffu, s, o);
        __shared__ float red[8];
        if ((tid & 31) == 0) red[tid >> 5] = s;
        __syncthreads();
        if ((tid & 63) == 0) {
            int w0 = tid >> 5;
            g_t1[b] = red[w0] + red[w0 + 1];
        }
    } else {
        int cp = (blockIdx.x - 256) * 2 + (tid >> 7);
        int d0 = (tid & 127) * 4;
        float4 lw = *reinterpret_cast<const float4*>(ls + (size_t)cp * 512 + d0);
        float4 pv = *reinterpret_cast<const float4*>(proto + (size_t)cp * 512 + d0);
        bool nzb = (lw.x != 0.f) || (lw.y != 0.f) || (lw.z != 0.f) || (lw.w != 0.f);
        unsigned nz = __ballot_sync(0xffffffffu, nzb);
        float acc;
        if (nz) {
            if ((tid & 31) == 0) atomicOr(&g_flag, 1);   // sticky across replays
            float w0 = expf(lw.x), w1 = expf(lw.y), w2 = expf(lw.z), w3 = expf(lw.w);
            __nv_bfloat162 hw[2], hp[2];
            hw[0] = __floats2bfloat162_rn(w0, w1);
            hw[1] = __floats2bfloat162_rn(w2, w3);
            hp[0] = __floats2bfloat162_rn(-2.0f * w0 * pv.x, -2.0f * w1 * pv.y);
            hp[1] = __floats2bfloat162_rn(-2.0f * w2 * pv.z, -2.0f * w3 * pv.w);
            *reinterpret_cast<uint2*>(g_Bm + (size_t)cp * KD + d0)       = *reinterpret_cast<uint2*>(hw);
            *reinterpret_cast<uint2*>(g_Bm + (size_t)cp * KD + 512 + d0) = *reinterpret_cast<uint2*>(hp);
            acc = w0 * pv.x * pv.x + w1 * pv.y * pv.y + w2 * pv.z * pv.z + w3 * pv.w * pv.w;
        } else {
            // warp-uniform fast path: w = exp(0) = 1 exactly
            uint2 ones = make_uint2(0x3F803F80u, 0x3F803F80u);   // bf16 1.0 x4
            __nv_bfloat162 hp[2];
            hp[0] = __floats2bfloat162_rn(-2.0f * pv.x, -2.0f * pv.y);
            hp[1] = __floats2bfloat162_rn(-2.0f * pv.z, -2.0f * pv.w);
            *reinterpret_cast<uint2*>(g_Bm + (size_t)cp * KD + d0)       = ones;
            *reinterpret_cast<uint2*>(g_Bm + (size_t)cp * KD + 512 + d0) = *reinterpret_cast<uint2*>(hp);
            acc = pv.x * pv.x + pv.y * pv.y + pv.z * pv.z + pv.w * pv.w;
        }
        #pragma unroll
        for (int o = 16; o > 0; o >>= 1) acc += __shfl_xor_sync(0xffffffffu, acc, o);
        __shared__ float red2[8];
        if ((tid & 31) == 0) red2[tid >> 5] = acc;
        __syncthreads();
        if ((tid & 127) == 0) {
            int w0i = (tid >> 7) * 4;
            g_t3[cp] = red2[w0i] + red2[w0i + 1] + red2[w0i + 2] + red2[w0i + 3];
        }
    }
}

// ---------------- GEMM + fused LSE (R15): BM=64/BN=40, 128 thr, BK=128 stages ----------------
// Stage = k-PAIR of 64-col sub-tiles: A 2x8KB = 16KB, B 2x5KB = 10KB.
// A stages at s*16384 (halves +0/+8192); B at 32768 + s*10240 (halves +0/+5120).
#define SA_OFF(s) ((s) * 16384)
#define SB_OFF(s) (32768 + (s) * 10240)
#define SMEM_TOTAL  (32768 + 2 * 10240)     // 53248
#define SST_STRIDE  44
#define T3_OFF      (64 * SST_STRIDE * 4)   // 11264 (inside stage-0 A, post-loop use)

__global__ __launch_bounds__(NTHREADS, 3) void gemm_lse_kernel(float* __restrict__ out) {
    extern __shared__ char smem[];
    const uint32_t sbase = smem_u32(smem);
    const int tid = threadIdx.x;
    const int wid = tid >> 5;    // 0..3
    const int lid = tid & 31;
    const int m0 = blockIdx.y * BM;
    const int n0 = blockIdx.x * BN;

    const int flag = g_flag;
    const int kp_start = flag ? 0 : 4;   // pair p covers k-tiles 2p,2p+1

    float t3reg = (tid < 40) ? g_t3[n0 + tid] : 0.f;

    // ---- load plan per stage: A 1024 chunks (8/thread), B 640 (5/thread)
    const uint4* a_gb[8];
    uint32_t a_off[8];
    #pragma unroll
    for (int i = 0; i < 8; i++) {
        int q = tid + i * NTHREADS;
        int h = q >> 9, qq = q & 511;
        int r = qq >> 3, c = qq & 7;
        a_gb[i] = reinterpret_cast<const uint4*>(g_A + (size_t)(m0 + r) * KD) + h * 8 + c;
        a_off[i] = (uint32_t)h * 8192u + sw128((uint32_t)r * 128u + (uint32_t)c * 16u);
    }
    const uint4* b_gb[5];
    uint32_t b_off[5];
    #pragma unroll
    for (int i = 0; i < 5; i++) {
        int q = tid + i * NTHREADS;    // [0,640) exactly
        int h = q / 320, qq = q % 320;
        int r = qq >> 3, c = qq & 7;
        b_gb[i] = reinterpret_cast<const uint4*>(g_Bm + (size_t)(n0 + r) * KD) + h * 8 + c;
        b_off[i] = (uint32_t)h * 5120u + sw128((uint32_t)r * 128u + (uint32_t)c * 16u);
    }

    // warp layout: 4 warps stacked in M; warp tile 16 x 40
    const int wm = wid * 16;

    float acc[5][4];
    #pragma unroll
    for (int nf = 0; nf < 5; nf++)
        #pragma unroll
        for (int i = 0; i < 4; i++) acc[nf][i] = 0.f;

    // ldmatrix swizzled offsets within a 64-col sub-tile
    const int l4 = lid & 15;
    uint32_t a_lm_off[4];
    uint32_t b4_off[2][4];
    uint32_t b2_off[4];
    #pragma unroll
    for (int ks = 0; ks < 4; ks++) {
        {
            uint32_t r = wm + (lid & 15);
            uint32_t ch = ks * 2 + (lid >> 4);
            a_lm_off[ks] = sw128(r * 128u + ch * 16u);
        }
        #pragma unroll
        for (int j = 0; j < 2; j++) {
            uint32_t r = j * 16 + (lid >> 4) * 8 + (lid & 7);
            uint32_t ch = ks * 2 + ((lid >> 3) & 1);
            b4_off[j][ks] = sw128(r * 128u + ch * 16u);
        }
        {
            uint32_t r = 32 + (l4 & 7);
            uint32_t ch = ks * 2 + (l4 >> 3);
            b2_off[ks] = sw128(r * 128u + ch * 16u);
        }
    }

    // ---- prologue: load pair kp_start ----
    {
        int s = kp_start & 1;
        uint32_t sa = sbase + SA_OFF(s), sb = sbase + SB_OFF(s);
        #pragma unroll
        for (int i = 0; i < 8; i++) CP_ASYNC16(sa + a_off[i], a_gb[i] + kp_start * 16);
        #pragma unroll
        for (int i = 0; i < 5; i++) CP_ASYNC16(sb + b_off[i], b_gb[i] + kp_start * 16);
        CP_COMMIT();
    }

    for (int kp = kp_start; kp < NKP; kp++) {
        if (kp + 1 < NKP) {
            int ns = (kp + 1) & 1;
            uint32_t sa = sbase + SA_OFF(ns), sb = sbase + SB_OFF(ns);
            #pragma unroll
            for (int i = 0; i < 8; i++) CP_ASYNC16(sa + a_off[i], a_gb[i] + (kp + 1) * 16);
            #pragma unroll
            for (int i = 0; i < 5; i++) CP_ASYNC16(sb + b_off[i], b_gb[i] + (kp + 1) * 16);
            CP_COMMIT();
            CP_WAIT1();
        } else {
            CP_WAIT0();
        }
        __syncthreads();   // one barrier per PAIR of k-tiles

        const uint32_t sa = sbase + SA_OFF(kp & 1);
        const uint32_t sb = sbase + SB_OFF(kp & 1);
        #pragma unroll
        for (int ks8 = 0; ks8 < 8; ks8++) {
            const int ks = ks8 & 3;
            const uint32_t ah = (ks8 >> 2) ? 8192u : 0u;
            const uint32_t bh = (ks8 >> 2) ? 5120u : 0u;
            uint32_t a[4], b[5][2];
            LDMATRIX_X4(a[0], a[1], a[2], a[3], sa + ah + a_lm_off[ks]);
            LDMATRIX_X4(b[0][0], b[0][1], b[1][0], b[1][1], sb + bh + b4_off[0][ks]);
            LDMATRIX_X4(b[2][0], b[2][1], b[3][0], b[3][1], sb + bh + b4_off[1][ks]);
            LDMATRIX_X2(b[4][0], b[4][1], sb + bh + b2_off[ks]);
            #pragma unroll
            for (int nf = 0; nf < 5; nf++)
                MMA_16816(acc[nf][0], acc[nf][1], acc[nf][2], acc[nf][3],
                          a[0], a[1], a[2], a[3], b[nf][0], b[nf][1]);
        }
        __syncthreads();
    }

    // ---- fused epilogue: fragments -> SMEM stage -> per-(row,class) logsumexp ----
    float* sst = reinterpret_cast<float*>(smem);            // [64][44]
    float* st3 = reinterpret_cast<float*>(smem + T3_OFF);   // [40]
    if (tid < 40) st3[tid] = t3reg;

    const int qr = lid >> 2;
    const int qc = (lid & 3) * 2;
    {
        int row = wm + qr;
        #pragma unroll
        for (int nf = 0; nf < 5; nf++) {
            int col = nf * 8 + qc;
            *reinterpret_cast<float2*>(&sst[row * SST_STRIDE + col]) =
                make_float2(acc[nf][0], acc[nf][1]);
            *reinterpret_cast<float2*>(&sst[(row + 8) * SST_STRIDE + col]) =
                make_float2(acc[nf][2], acc[nf][3]);
        }
    }
    __syncthreads();

    // 64 rows x 4 classes = 256 tasks, 2 per thread
    const int c0 = blockIdx.x * 4;
    #pragma unroll
    for (int i = 0; i < 2; i++) {
        int task = tid + i * NTHREADS;
        int row = task >> 2;
        int cls = task & 3;
        const float* sp = &sst[row * SST_STRIDE + cls * 10];
        const float* tp = &st3[cls * 10];
        float v[10], mx = -3.4e38f;
        #pragma unroll
        for (int p = 0; p < 10; p++) {
            v[p] = -(sp[p] + tp[p]);
            mx = fmaxf(mx, v[p]);
        }
        float s = 0.f;
        #pragma unroll
        for (int p = 0; p < 10; p++) s += expf(v[p] - mx);
        float t1v = flag ? 0.f : g_t1[m0 + row];   // fast path: t1 slid out of lse
        out[(size_t)(m0 + row) * 100 + c0 + cls] = mx + logf(s) - t1v;
    }
}

// ---------------- launch ----------------
extern "C" void kernel_launch(void* const* d_in, const int* in_sizes, int n_in,
                              void* d_out, int out_size) {
    const float* x     = (const float*)d_in[0];  // (1024, 512)
    const float* proto = (const float*)d_in[1];  // (100, 10, 512)
    const float* ls    = (const float*)d_in[2];  // (100, 10, 512)
    float* out = (float*)d_out;                  // (1024, 100)

    cudaFuncSetAttribute(gemm_lse_kernel, cudaFuncAttributeMaxDynamicSharedMemorySize, SMEM_TOTAL);

    prep_kernel<<<756, 256>>>(x, proto, ls);     // x+t1 (256 blocks) | proto+t3+flag (500)
    gemm_lse_kernel<<<dim3(25, MB / BM), NTHREADS, SMEM_TOTAL>>>(out);
}